// round 1
// baseline (speedup 1.0000x reference)
#include <cuda_runtime.h>
#include <math.h>

#define S_  64
#define B_  64
#define K_  512
#define H_  512
#define E_  512
#define A_  512
#define V_  32000
#define G3H 1536

// ---------------- scratch (static device memory; no allocations) ----------------
__device__ float g_keys[S_ * B_ * A_];       // keys_proj [s][b][a]   8.4 MB
__device__ float g_qW[B_ * A_];              // h @ Wq
__device__ float g_scores[S_ * B_];          // [s][b]
__device__ float g_rnn_in[B_ * (E_ + K_)];   // [x_emb | ctx]
__device__ float g_mlp_in[B_ * (E_ + H_ + K_)]; // [x_emb | h_new | ctx]
__device__ float g_h[B_ * H_];
__device__ float g_gi[B_ * G3H];
__device__ float g_gh[B_ * G3H];
__device__ float g_hidden[B_ * H_];
__device__ float g_logits[B_ * V_];          // 8.2 MB
__device__ float g_part[8 * B_ * G3H];       // split-K partials (max N=1536)
__device__ float g_WihT[(E_ + K_) * G3H];    // W_ih transposed (1024 x 1536)
__device__ float g_WhhT[H_ * G3H];           // W_hh transposed (512 x 1536)
__device__ int   g_tok[B_];

// ---------------- packed f32x2 FMA (ptxas never auto-fuses this) ----------------
__device__ __forceinline__ float2 ffma2(float2 a, float2 b, float2 c) {
    unsigned long long ua = *reinterpret_cast<unsigned long long*>(&a);
    unsigned long long ub = *reinterpret_cast<unsigned long long*>(&b);
    unsigned long long uc = *reinterpret_cast<unsigned long long*>(&c);
    unsigned long long ud;
    asm("fma.rn.f32x2 %0, %1, %2, %3;" : "=l"(ud) : "l"(ua), "l"(ub), "l"(uc));
    return *reinterpret_cast<float2*>(&ud);
}

// ---------------- generic NN GEMM: C[M,N] = A[M,K] @ B[K,N] ----------------
// Tile 64(M) x 128(N), BK=8, 256 threads, 4m x 8n micro-tile, n-paired FFMA2.
// grid = (N/128, M/64, splitZ). splitZ>1 writes partials (caller passes bias=0,act=0).
__global__ void gemm64(const float* __restrict__ A, const float* __restrict__ B,
                       float* __restrict__ C, const float* __restrict__ bias,
                       int K, int N, int act)
{
    __shared__ float As2[8][128];   // duplicated pairs: As2[k][2m]=As2[k][2m+1]=A[m][k]
    __shared__ float Bs[8][128];

    const int tid = threadIdx.x;
    const int Keff = K / gridDim.z;
    const float* Ap = A + (size_t)blockIdx.z * Keff;
    const float* Bp = B + (size_t)blockIdx.z * Keff * N;
    float* Cp = C + (size_t)blockIdx.z * 64 * N;   // grid.z>1 only used with grid.y==1

    const int m_base = blockIdx.y * 64;
    const int n_base = blockIdx.x * 128;

    const int ty = tid >> 4, tx = tid & 15;
    const int m0 = ty * 4, n0 = tx * 8;

    const int am = tid >> 2, ak = (tid & 3) * 2;
    const int bk = tid >> 5, bn = (tid & 31) * 4;

    const float* Aload = Ap + (size_t)(m_base + am) * K + ak;
    const float* Bload = Bp + (size_t)bk * N + n_base + bn;

    float2 acc[4][4];
#pragma unroll
    for (int i = 0; i < 4; i++)
#pragma unroll
        for (int j = 0; j < 4; j++) acc[i][j] = make_float2(0.f, 0.f);

    for (int k0 = 0; k0 < Keff; k0 += 8) {
        float2 av = *(const float2*)(Aload + k0);
        *(float2*)&As2[ak    ][2 * am] = make_float2(av.x, av.x);
        *(float2*)&As2[ak + 1][2 * am] = make_float2(av.y, av.y);
        *(float4*)&Bs[bk][bn] = *(const float4*)(Bload + (size_t)k0 * N);
        __syncthreads();
#pragma unroll
        for (int kk = 0; kk < 8; kk++) {
            float2 ad[4];
#pragma unroll
            for (int i = 0; i < 4; i++) ad[i] = *(const float2*)&As2[kk][2 * (m0 + i)];
            float4 b0 = *(const float4*)&Bs[kk][n0];
            float4 b1 = *(const float4*)&Bs[kk][n0 + 4];
            float2 bp[4];
            bp[0] = make_float2(b0.x, b0.y); bp[1] = make_float2(b0.z, b0.w);
            bp[2] = make_float2(b1.x, b1.y); bp[3] = make_float2(b1.z, b1.w);
#pragma unroll
            for (int i = 0; i < 4; i++)
#pragma unroll
                for (int j = 0; j < 4; j++)
                    acc[i][j] = ffma2(ad[i], bp[j], acc[i][j]);
        }
        __syncthreads();
    }

#pragma unroll
    for (int i = 0; i < 4; i++) {
#pragma unroll
        for (int j = 0; j < 4; j++) {
            int n = n_base + n0 + 2 * j;
            float2 v = acc[i][j];
            if (bias) { v.x += bias[n]; v.y += bias[n + 1]; }
            if (act)  { v.x = tanhf(v.x); v.y = tanhf(v.y); }
            *(float2*)&Cp[(size_t)(m_base + m0 + i) * N + n] = v;
        }
    }
}

// Sum split-K partials, add bias, optional tanh. size = 64*N elements.
__global__ void reduce_split(float* __restrict__ C, const float* __restrict__ part,
                             const float* __restrict__ bias, int N, int nz, int act)
{
    int idx = blockIdx.x * blockDim.x + threadIdx.x;
    if (idx >= 64 * N) return;
    int n = idx % N;
    float s = 0.f;
    for (int z = 0; z < nz; z++) s += part[(size_t)z * 64 * N + idx];
    if (bias) s += bias[n];
    if (act)  s = tanhf(s);
    C[idx] = s;
}

// out[c][r] = in[r][c]; R,C multiples of 32; block (32,8), grid (C/32, R/32)
__global__ void transpose_k(const float* __restrict__ in, float* __restrict__ out,
                            int R, int C)
{
    __shared__ float tile[32][33];
    int c = blockIdx.x * 32 + threadIdx.x;
    int r0 = blockIdx.y * 32;
    for (int i = threadIdx.y; i < 32; i += 8)
        tile[i][threadIdx.x] = in[(size_t)(r0 + i) * C + c];
    __syncthreads();
    int r2 = blockIdx.y * 32 + threadIdx.x;
    int c0 = blockIdx.x * 32;
    for (int i = threadIdx.y; i < 32; i += 8)
        out[(size_t)(c0 + i) * R + r2] = tile[threadIdx.x][i];
}

__global__ void init_state(const float* __restrict__ h0)
{
    int i = blockIdx.x * blockDim.x + threadIdx.x;
    if (i < B_) g_tok[i] = 1;                  // SOS
    if (i < B_ * H_) g_h[i] = h0[i];           // L=1
}

__global__ void gather_emb(const float* __restrict__ emb)
{
    int b = blockIdx.x;
    int tok = g_tok[b];
    const float* src = emb + (size_t)tok * E_;
    for (int i = threadIdx.x; i < E_; i += blockDim.x) {
        float v = src[i];
        g_rnn_in[b * (E_ + K_) + i] = v;
        g_mlp_in[b * (E_ + H_ + K_) + i] = v;
    }
}

// one warp per (s,b): score = sum_a tanh(qW[b,a]+keys[s,b,a]) * v_att[a]
__global__ void attn_scores(const float* __restrict__ v_att)
{
    int p = blockIdx.x * 8 + (threadIdx.x >> 5);
    int lane = threadIdx.x & 31;
    int s = p >> 6, b = p & 63;
    const float* kp = g_keys + (size_t)(s * B_ + b) * A_;
    const float* qw = g_qW + b * A_;
    float acc = 0.f;
    for (int a = lane; a < A_; a += 32)
        acc += tanhf(qw[a] + kp[a]) * v_att[a];
#pragma unroll
    for (int o = 16; o; o >>= 1) acc += __shfl_xor_sync(0xffffffffu, acc, o);
    if (lane == 0) g_scores[s * B_ + b] = acc;
}

// one block per b: softmax over s (64), then ctx[b,k] = sum_s attn*enc[s,b,k]
__global__ void softmax_ctx(const float* __restrict__ enc)
{
    int b = blockIdx.x;
    int tid = threadIdx.x;
    __shared__ float attn[S_];
    __shared__ float red[8];
    float v = (tid < S_) ? g_scores[tid * B_ + b] : -1e30f;
    int lane = tid & 31, w = tid >> 5;
    float m = v;
#pragma unroll
    for (int o = 16; o; o >>= 1) m = fmaxf(m, __shfl_xor_sync(0xffffffffu, m, o));
    if (!lane) red[w] = m;
    __syncthreads();
    if (tid == 0) {
        float M = red[0];
        for (int i = 1; i < 8; i++) M = fmaxf(M, red[i]);
        red[0] = M;
    }
    __syncthreads();
    float mx = red[0];
    float e = (tid < S_) ? expf(v - mx) : 0.f;
    float s = e;
#pragma unroll
    for (int o = 16; o; o >>= 1) s += __shfl_xor_sync(0xffffffffu, s, o);
    __syncthreads();
    if (!lane) red[w] = s;
    __syncthreads();
    if (tid == 0) {
        float t = 0.f;
        for (int i = 0; i < 8; i++) t += red[i];
        red[0] = t;
    }
    __syncthreads();
    if (tid < S_) attn[tid] = e / red[0];
    __syncthreads();
    for (int k = tid; k < K_; k += blockDim.x) {
        float acc = 0.f;
        const float* ep = enc + (size_t)b * K_ + k;
#pragma unroll 8
        for (int s2 = 0; s2 < S_; s2++) acc += attn[s2] * ep[(size_t)s2 * (B_ * K_)];
        g_rnn_in[b * (E_ + K_) + E_ + k] = acc;
        g_mlp_in[b * (E_ + H_ + K_) + E_ + H_ + k] = acc;
    }
}

__global__ void gru_combine()
{
    int idx = blockIdx.x * blockDim.x + threadIdx.x;
    if (idx >= B_ * H_) return;
    int b = idx >> 9, j = idx & 511;
    const float* gi = g_gi + b * G3H;
    const float* gh = g_gh + b * G3H;
    float r = 1.f / (1.f + expf(-(gi[j] + gh[j])));
    float z = 1.f / (1.f + expf(-(gi[j + H_] + gh[j + H_])));
    float n = tanhf(gi[j + 2 * H_] + r * gh[j + 2 * H_]);
    float h = g_h[idx];
    float hn = (1.f - z) * n + z * h;
    g_h[idx] = hn;
    g_mlp_in[b * (E_ + H_ + K_) + E_ + j] = hn;
}

// one block per b (512 thr): max+argmax, sum-exp, write probs, feed next token
__global__ void softmax_v(float* __restrict__ out, int t, int T)
{
    int b = blockIdx.x;
    int tid = threadIdx.x;
    const float* lg = g_logits + (size_t)b * V_;
    float* op = out + ((size_t)b * T + t) * V_;
    int lane = tid & 31, w = tid >> 5;

    float bm = -1e30f; int bi = 0;
    for (int v = tid; v < V_; v += 512) {
        float x = lg[v];
        if (x > bm) { bm = x; bi = v; }
    }
    __shared__ float smax[16]; __shared__ int sidx[16]; __shared__ float ssum[16];
#pragma unroll
    for (int o = 16; o; o >>= 1) {
        float om = __shfl_xor_sync(0xffffffffu, bm, o);
        int   oi = __shfl_xor_sync(0xffffffffu, bi, o);
        if (om > bm || (om == bm && oi < bi)) { bm = om; bi = oi; }
    }
    if (!lane) { smax[w] = bm; sidx[w] = bi; }
    __syncthreads();
    if (tid == 0) {
        float M = smax[0]; int I = sidx[0];
        for (int i = 1; i < 16; i++)
            if (smax[i] > M || (smax[i] == M && sidx[i] < I)) { M = smax[i]; I = sidx[i]; }
        smax[0] = M;
        g_tok[b] = I;
    }
    __syncthreads();
    float mx = smax[0];

    float s = 0.f;
    for (int v = tid; v < V_; v += 512) s += expf(lg[v] - mx);
#pragma unroll
    for (int o = 16; o; o >>= 1) s += __shfl_xor_sync(0xffffffffu, s, o);
    if (!lane) ssum[w] = s;
    __syncthreads();
    if (tid == 0) {
        float tt = 0.f;
        for (int i = 0; i < 16; i++) tt += ssum[i];
        ssum[0] = tt;
    }
    __syncthreads();
    float inv = 1.f / ssum[0];
    for (int v = tid; v < V_; v += 512) op[v] = expf(lg[v] - mx) * inv;
}

// ---------------- launch ----------------
extern "C" void kernel_launch(void* const* d_in, const int* in_sizes, int n_in,
                              void* d_out, int out_size)
{
    const float* enc   = (const float*)d_in[0];
    const float* h0    = (const float*)d_in[1];
    const float* emb   = (const float*)d_in[2];
    const float* Wq    = (const float*)d_in[3];
    const float* Wk    = (const float*)d_in[4];
    const float* v_att = (const float*)d_in[5];
    const float* W_ih  = (const float*)d_in[6];
    const float* W_hh  = (const float*)d_in[7];
    const float* b_ih  = (const float*)d_in[8];
    const float* b_hh  = (const float*)d_in[9];
    const float* W1    = (const float*)d_in[10];
    const float* b1    = (const float*)d_in[11];
    const float* W2    = (const float*)d_in[12];
    const float* b2    = (const float*)d_in[13];
    float* out = (float*)d_out;
    const int T = out_size / (B_ * V_);

    float *p_keys, *p_qW, *p_rnn, *p_mlp, *p_h, *p_gi, *p_gh, *p_hidden,
          *p_logits, *p_part, *p_WihT, *p_WhhT;
    cudaGetSymbolAddress((void**)&p_keys,   g_keys);
    cudaGetSymbolAddress((void**)&p_qW,     g_qW);
    cudaGetSymbolAddress((void**)&p_rnn,    g_rnn_in);
    cudaGetSymbolAddress((void**)&p_mlp,    g_mlp_in);
    cudaGetSymbolAddress((void**)&p_h,      g_h);
    cudaGetSymbolAddress((void**)&p_gi,     g_gi);
    cudaGetSymbolAddress((void**)&p_gh,     g_gh);
    cudaGetSymbolAddress((void**)&p_hidden, g_hidden);
    cudaGetSymbolAddress((void**)&p_logits, g_logits);
    cudaGetSymbolAddress((void**)&p_part,   g_part);
    cudaGetSymbolAddress((void**)&p_WihT,   g_WihT);
    cudaGetSymbolAddress((void**)&p_WhhT,   g_WhhT);

    // one-time (per replay) prep
    init_state<<<(B_ * H_ + 255) / 256, 256>>>(h0);
    transpose_k<<<dim3((E_ + K_) / 32, G3H / 32), dim3(32, 8)>>>(W_ih, p_WihT, G3H, E_ + K_);
    transpose_k<<<dim3(H_ / 32, G3H / 32), dim3(32, 8)>>>(W_hh, p_WhhT, G3H, H_);
    // keys_proj: (S*B) x A = enc(4096x512) @ Wk(512x512)
    gemm64<<<dim3(A_ / 128, (S_ * B_) / 64, 1), 256>>>(enc, Wk, p_keys, nullptr, K_, A_, 0);

    for (int t = 0; t < T; t++) {
        gather_emb<<<B_, 256>>>(emb);

        // qW = h @ Wq   (split-K x8)
        gemm64<<<dim3(A_ / 128, 1, 8), 256>>>(p_h, Wq, p_part, nullptr, H_, A_, 0);
        reduce_split<<<(B_ * A_ + 255) / 256, 256>>>(p_qW, p_part, nullptr, A_, 8, 0);

        attn_scores<<<(S_ * B_) / 8, 256>>>(v_att);
        softmax_ctx<<<B_, 256>>>(enc);

        // gi = rnn_in @ W_ih^T + b_ih
        gemm64<<<dim3(G3H / 128, 1, 8), 256>>>(p_rnn, p_WihT, p_part, nullptr, E_ + K_, G3H, 0);
        reduce_split<<<(B_ * G3H + 255) / 256, 256>>>(p_gi, p_part, b_ih, G3H, 8, 0);
        // gh = h @ W_hh^T + b_hh
        gemm64<<<dim3(G3H / 128, 1, 8), 256>>>(p_h, p_WhhT, p_part, nullptr, H_, G3H, 0);
        reduce_split<<<(B_ * G3H + 255) / 256, 256>>>(p_gh, p_part, b_hh, G3H, 8, 0);

        gru_combine<<<(B_ * H_ + 255) / 256, 256>>>();

        // hidden = tanh(mlp_in @ W1 + b1)
        gemm64<<<dim3(H_ / 128, 1, 8), 256>>>(p_mlp, W1, p_part, nullptr, E_ + H_ + K_, H_, 0);
        reduce_split<<<(B_ * H_ + 255) / 256, 256>>>(p_hidden, p_part, b1, H_, 8, 1);

        // logits = hidden @ W2 + b2   (the big one: N=32000)
        gemm64<<<dim3(V_ / 128, 1, 1), 256>>>(p_hidden, W2, p_logits, b2, H_, V_, 0);

        softmax_v<<<B_, 512>>>(out, t, T);
    }
}

// round 3
// speedup vs baseline: 1.8896x; 1.8896x over previous
#include <cuda_runtime.h>
#include <math.h>

#define S_  64
#define B_  64
#define K_  512
#define H_  512
#define E_  512
#define A_  512
#define V_  32000
#define G3H 1536

// ---------------- scratch (static device memory; no allocations) ----------------
__device__ float g_keys[S_ * B_ * A_];          // keys_proj [s][b][a]
__device__ float g_qW[B_ * A_];                 // h @ Wq
__device__ float g_scores[S_ * B_];
__device__ float g_rnn_in[B_ * (E_ + K_)];      // [x_emb | ctx]
__device__ float g_mlp_in[B_ * (E_ + H_ + K_)]; // [x_emb | h_new | ctx]
__device__ float g_h[B_ * H_];
__device__ float g_hidden[B_ * H_];
__device__ float g_logits[B_ * V_];
__device__ float g_partA[8 * B_ * G3H];         // split-K partials
__device__ float g_partB[8 * B_ * G3H];
__device__ float g_WihT[(E_ + K_) * G3H];       // W_ih^T
__device__ float g_WhhT[H_ * G3H];              // W_hh^T
__device__ int   g_tok[B_];

// ---------------- fast math (err ~1e-6, safe vs 1e-3 tolerance) ----------------
__device__ __forceinline__ float ftanh(float x) {
    float t = __expf(-2.f * fabsf(x));
    float r = __fdividef(1.f - t, 1.f + t);
    return copysignf(r, x);
}
__device__ __forceinline__ float fsigmoid(float x) {
    return __fdividef(1.f, 1.f + __expf(-x));
}

// ---------------- packed f32x2 FMA ----------------
__device__ __forceinline__ float2 ffma2(float2 a, float2 b, float2 c) {
    unsigned long long ua = *reinterpret_cast<unsigned long long*>(&a);
    unsigned long long ub = *reinterpret_cast<unsigned long long*>(&b);
    unsigned long long uc = *reinterpret_cast<unsigned long long*>(&c);
    unsigned long long ud;
    asm("fma.rn.f32x2 %0, %1, %2, %3;" : "=l"(ud) : "l"(ua), "l"(ub), "l"(uc));
    return *reinterpret_cast<float2*>(&ud);
}

// ---------------- NN GEMM: C[M,N] = A[M,K] @ B[K,N] ----------------
// Tile 64(M) x 128(N), BK=16, 256 threads, double-buffered smem,
// micro-tile 4m x (4n + 4n @ +64) with paired FFMA2. Conflict-free smem.
// grid = (N/128, M/64, splitZ). splitZ>1 writes partials at z*64*N.
__device__ __forceinline__ void gemm_compute(
    const float (*As2)[130], const float (*Bs)[128],
    int m0, int bn, float2 acc[4][4])
{
#pragma unroll
    for (int kk = 0; kk < 16; kk++) {
        float2 ad[4];
#pragma unroll
        for (int i = 0; i < 4; i++)
            ad[i] = *(const float2*)&As2[kk][2 * (m0 + i)];
        float4 b0 = *(const float4*)&Bs[kk][bn];
        float4 b1 = *(const float4*)&Bs[kk][bn + 64];
        float2 bp[4];
        bp[0] = make_float2(b0.x, b0.y); bp[1] = make_float2(b0.z, b0.w);
        bp[2] = make_float2(b1.x, b1.y); bp[3] = make_float2(b1.z, b1.w);
#pragma unroll
        for (int i = 0; i < 4; i++)
#pragma unroll
            for (int j = 0; j < 4; j++)
                acc[i][j] = ffma2(ad[i], bp[j], acc[i][j]);
    }
}

__global__ void __launch_bounds__(256, 3)
gemm64(const float* __restrict__ A, const float* __restrict__ B,
       float* __restrict__ C, const float* __restrict__ bias,
       int K, int N, int act)
{
    __shared__ __align__(16) float As2[2][16][130]; // duplicated pairs, padded
    __shared__ __align__(16) float Bs[2][16][128];

    const int tid = threadIdx.x;
    const int Keff = K / gridDim.z;
    const float* Ap = A + (size_t)blockIdx.z * Keff;
    const float* Bp = B + (size_t)blockIdx.z * Keff * N;
    float* Cp = C + (size_t)blockIdx.z * 64 * N;

    const int m_base = blockIdx.y * 64;
    const int n_base = blockIdx.x * 128;

    const int ty = tid >> 4, tx = tid & 15;
    const int m0 = ty * 4;
    const int bn = tx * 4;

    const int am = tid >> 2, ak = (tid & 3) * 4;
    const int bk0 = tid >> 4;

    const float* Aload = Ap + (size_t)(m_base + am) * K + ak;
    const float* Bload = Bp + (size_t)bk0 * N + n_base + bn;

    float2 acc[4][4];
#pragma unroll
    for (int i = 0; i < 4; i++)
#pragma unroll
        for (int j = 0; j < 4; j++) acc[i][j] = make_float2(0.f, 0.f);

    // preload tile 0
    float4 aR  = *(const float4*)Aload;
    float4 bR0 = *(const float4*)Bload;
    float4 bR1 = *(const float4*)(Bload + 64);

    *(float2*)&As2[0][ak + 0][2 * am] = make_float2(aR.x, aR.x);
    *(float2*)&As2[0][ak + 1][2 * am] = make_float2(aR.y, aR.y);
    *(float2*)&As2[0][ak + 2][2 * am] = make_float2(aR.z, aR.z);
    *(float2*)&As2[0][ak + 3][2 * am] = make_float2(aR.w, aR.w);
    *(float4*)&Bs[0][bk0][bn]      = bR0;
    *(float4*)&Bs[0][bk0][bn + 64] = bR1;
    __syncthreads();

    int buf = 0;
    for (int k0 = 16; k0 < Keff; k0 += 16) {
        float4 aN  = *(const float4*)(Aload + k0);
        float4 bN0 = *(const float4*)(Bload + (size_t)k0 * N);
        float4 bN1 = *(const float4*)(Bload + (size_t)k0 * N + 64);

        gemm_compute(As2[buf], Bs[buf], m0, bn, acc);

        int nb = buf ^ 1;
        *(float2*)&As2[nb][ak + 0][2 * am] = make_float2(aN.x, aN.x);
        *(float2*)&As2[nb][ak + 1][2 * am] = make_float2(aN.y, aN.y);
        *(float2*)&As2[nb][ak + 2][2 * am] = make_float2(aN.z, aN.z);
        *(float2*)&As2[nb][ak + 3][2 * am] = make_float2(aN.w, aN.w);
        *(float4*)&Bs[nb][bk0][bn]      = bN0;
        *(float4*)&Bs[nb][bk0][bn + 64] = bN1;
        __syncthreads();
        buf = nb;
    }
    gemm_compute(As2[buf], Bs[buf], m0, bn, acc);

#pragma unroll
    for (int i = 0; i < 4; i++) {
#pragma unroll
        for (int j = 0; j < 4; j++) {
            int n = n_base + bn + (j & 1) * 2 + (j >> 1) * 64;
            float2 v = acc[i][j];
            if (bias) { v.x += bias[n]; v.y += bias[n + 1]; }
            if (act)  { v.x = tanhf(v.x); v.y = tanhf(v.y); }
            *(float2*)&Cp[(size_t)(m_base + m0 + i) * N + n] = v;
        }
    }
}

// Sum split-K partials, add bias, optional tanh. 64*N elements.
__global__ void reduce_split(float* __restrict__ C, const float* __restrict__ part,
                             const float* __restrict__ bias, int N, int nz, int act)
{
    int idx = blockIdx.x * blockDim.x + threadIdx.x;
    if (idx >= 64 * N) return;
    int n = idx % N;
    float s = 0.f;
    for (int z = 0; z < nz; z++) s += part[(size_t)z * 64 * N + idx];
    if (bias) s += bias[n];
    if (act)  s = tanhf(s);
    C[idx] = s;
}

// out[c][r] = in[r][c]
__global__ void transpose_k(const float* __restrict__ in, float* __restrict__ out,
                            int R, int C)
{
    __shared__ float tile[32][33];
    int c = blockIdx.x * 32 + threadIdx.x;
    int r0 = blockIdx.y * 32;
    for (int i = threadIdx.y; i < 32; i += 8)
        tile[i][threadIdx.x] = in[(size_t)(r0 + i) * C + c];
    __syncthreads();
    int r2 = blockIdx.y * 32 + threadIdx.x;
    int c0 = blockIdx.x * 32;
    for (int i = threadIdx.y; i < 32; i += 8)
        out[(size_t)(c0 + i) * R + r2] = tile[threadIdx.x][i];
}

__global__ void init_state(const float* __restrict__ h0)
{
    int i = blockIdx.x * blockDim.x + threadIdx.x;
    if (i < B_) g_tok[i] = 1;                  // SOS
    if (i < B_ * H_) g_h[i] = h0[i];
}

// blocks 0..63: gather embedding; blocks 64..191: reduce qW split-K partials
__global__ void pre_attn(const float* __restrict__ emb)
{
    int blk = blockIdx.x;
    if (blk < 64) {
        int b = blk;
        int tok = g_tok[b];
        const float* src = emb + (size_t)tok * E_;
        for (int i = threadIdx.x; i < E_; i += 256) {
            float v = src[i];
            g_rnn_in[b * (E_ + K_) + i] = v;
            g_mlp_in[b * (E_ + H_ + K_) + i] = v;
        }
    } else {
        int idx = (blk - 64) * 256 + threadIdx.x;   // B_*A_ = 32768 = 128*256
        float s = 0.f;
#pragma unroll
        for (int z = 0; z < 8; z++) s += g_partA[(size_t)z * B_ * A_ + idx];
        g_qW[idx] = s;
    }
}

// one warp per (s,b): score = sum_a tanh(qW[b,a]+keys[s,b,a]) * v_att[a]
__global__ void attn_scores(const float* __restrict__ v_att)
{
    int p = blockIdx.x * 8 + (threadIdx.x >> 5);
    int lane = threadIdx.x & 31;
    int s = p >> 6, b = p & 63;
    const float4* kp = (const float4*)(g_keys + (size_t)(s * B_ + b) * A_);
    const float4* qw = (const float4*)(g_qW + b * A_);
    const float4* va = (const float4*)v_att;
    float acc = 0.f;
#pragma unroll
    for (int a = lane; a < A_ / 4; a += 32) {
        float4 k4 = kp[a], q4 = qw[a], v4 = va[a];
        acc += ftanh(q4.x + k4.x) * v4.x + ftanh(q4.y + k4.y) * v4.y
             + ftanh(q4.z + k4.z) * v4.z + ftanh(q4.w + k4.w) * v4.w;
    }
#pragma unroll
    for (int o = 16; o; o >>= 1) acc += __shfl_xor_sync(0xffffffffu, acc, o);
    if (lane == 0) g_scores[s * B_ + b] = acc;
}

// one block per b: softmax over s, then ctx[b,k] = sum_s attn*enc[s,b,k]
__global__ void softmax_ctx(const float* __restrict__ enc)
{
    int b = blockIdx.x;
    int tid = threadIdx.x;
    __shared__ float attn[S_];
    __shared__ float red[8];
    float v = (tid < S_) ? g_scores[tid * B_ + b] : -1e30f;
    int lane = tid & 31, w = tid >> 5;
    float m = v;
#pragma unroll
    for (int o = 16; o; o >>= 1) m = fmaxf(m, __shfl_xor_sync(0xffffffffu, m, o));
    if (!lane) red[w] = m;
    __syncthreads();
    if (tid == 0) {
        float M = red[0];
        for (int i = 1; i < 8; i++) M = fmaxf(M, red[i]);
        red[0] = M;
    }
    __syncthreads();
    float mx = red[0];
    float e = (tid < S_) ? __expf(v - mx) : 0.f;
    float s = e;
#pragma unroll
    for (int o = 16; o; o >>= 1) s += __shfl_xor_sync(0xffffffffu, s, o);
    __syncthreads();
    if (!lane) red[w] = s;
    __syncthreads();
    if (tid == 0) {
        float t = 0.f;
        for (int i = 0; i < 8; i++) t += red[i];
        red[0] = t;
    }
    __syncthreads();
    if (tid < S_) attn[tid] = __fdividef(e, red[0]);
    __syncthreads();
    for (int k = tid; k < K_; k += blockDim.x) {
        float acc = 0.f;
        const float* ep = enc + (size_t)b * K_ + k;
#pragma unroll 8
        for (int s2 = 0; s2 < S_; s2++) acc += attn[s2] * ep[(size_t)s2 * (B_ * K_)];
        g_rnn_in[b * (E_ + K_) + E_ + k] = acc;
        g_mlp_in[b * (E_ + H_ + K_) + E_ + H_ + k] = acc;
    }
}

// fused: sum gi/gh split-K partials + biases + GRU cell + write h, mlp_in
__global__ void gru_fused(const float* __restrict__ b_ih, const float* __restrict__ b_hh)
{
    int idx = blockIdx.x * 256 + threadIdx.x;   // B_*H_ = 32768
    int b = idx >> 9, j = idx & 511;
    float gir = 0.f, giz = 0.f, gin = 0.f, ghr = 0.f, ghz = 0.f, ghn = 0.f;
#pragma unroll
    for (int z = 0; z < 8; z++) {
        const float* pa = g_partA + (size_t)z * B_ * G3H + b * G3H;
        const float* pb = g_partB + (size_t)z * B_ * G3H + b * G3H;
        gir += pa[j]; giz += pa[j + H_]; gin += pa[j + 2 * H_];
        ghr += pb[j]; ghz += pb[j + H_]; ghn += pb[j + 2 * H_];
    }
    gir += b_ih[j]; giz += b_ih[j + H_]; gin += b_ih[j + 2 * H_];
    ghr += b_hh[j]; ghz += b_hh[j + H_]; ghn += b_hh[j + 2 * H_];
    float r  = fsigmoid(gir + ghr);
    float z_ = fsigmoid(giz + ghz);
    float n  = ftanh(gin + r * ghn);
    float h  = g_h[idx];
    float hn = (1.f - z_) * n + z_ * h;
    g_h[idx] = hn;
    g_mlp_in[b * (E_ + H_ + K_) + E_ + j] = hn;
}

// one block per b (512 thr): max+argmax, sum-exp, write probs, feed next token
__global__ void softmax_v(float* __restrict__ out, int t, int T)
{
    int b = blockIdx.x;
    int tid = threadIdx.x;
    const float* lg = g_logits + (size_t)b * V_;
    float* op = out + ((size_t)b * T + t) * V_;
    int lane = tid & 31, w = tid >> 5;

    float bm = -1e30f; int bi = 0;
    for (int v = tid; v < V_; v += 512) {
        float x = lg[v];
        if (x > bm) { bm = x; bi = v; }
    }
    __shared__ float smax[16]; __shared__ int sidx[16]; __shared__ float ssum[16];
#pragma unroll
    for (int o = 16; o; o >>= 1) {
        float om = __shfl_xor_sync(0xffffffffu, bm, o);
        int   oi = __shfl_xor_sync(0xffffffffu, bi, o);
        if (om > bm || (om == bm && oi < bi)) { bm = om; bi = oi; }
    }
    if (!lane) { smax[w] = bm; sidx[w] = bi; }
    __syncthreads();
    if (tid == 0) {
        float M = smax[0]; int I = sidx[0];
        for (int i = 1; i < 16; i++)
            if (smax[i] > M || (smax[i] == M && sidx[i] < I)) { M = smax[i]; I = sidx[i]; }
        smax[0] = M;
        g_tok[b] = I;
    }
    __syncthreads();
    float mx = smax[0];

    float s = 0.f;
    for (int v = tid; v < V_; v += 512) s += __expf(lg[v] - mx);
#pragma unroll
    for (int o = 16; o; o >>= 1) s += __shfl_xor_sync(0xffffffffu, s, o);
    if (!lane) ssum[w] = s;
    __syncthreads();
    if (tid == 0) {
        float tt = 0.f;
        for (int i = 0; i < 16; i++) tt += ssum[i];
        ssum[0] = tt;
    }
    __syncthreads();
    float inv = __fdividef(1.f, ssum[0]);
    for (int v = tid; v < V_; v += 512) op[v] = __expf(lg[v] - mx) * inv;
}

// ---------------- launch ----------------
extern "C" void kernel_launch(void* const* d_in, const int* in_sizes, int n_in,
                              void* d_out, int out_size)
{
    const float* enc   = (const float*)d_in[0];
    const float* h0    = (const float*)d_in[1];
    const float* emb   = (const float*)d_in[2];
    const float* Wq    = (const float*)d_in[3];
    const float* Wk    = (const float*)d_in[4];
    const float* v_att = (const float*)d_in[5];
    const float* W_ih  = (const float*)d_in[6];
    const float* W_hh  = (const float*)d_in[7];
    const float* b_ih  = (const float*)d_in[8];
    const float* b_hh  = (const float*)d_in[9];
    const float* W1    = (const float*)d_in[10];
    const float* b1    = (const float*)d_in[11];
    const float* W2    = (const float*)d_in[12];
    const float* b2    = (const float*)d_in[13];
    float* out = (float*)d_out;
    const int T = out_size / (B_ * V_);

    float *p_keys, *p_rnn, *p_mlp, *p_h, *p_hidden, *p_logits,
          *p_partA, *p_partB, *p_WihT, *p_WhhT;
    cudaGetSymbolAddress((void**)&p_keys,   g_keys);
    cudaGetSymbolAddress((void**)&p_rnn,    g_rnn_in);
    cudaGetSymbolAddress((void**)&p_mlp,    g_mlp_in);
    cudaGetSymbolAddress((void**)&p_h,      g_h);
    cudaGetSymbolAddress((void**)&p_hidden, g_hidden);
    cudaGetSymbolAddress((void**)&p_logits, g_logits);
    cudaGetSymbolAddress((void**)&p_partA,  g_partA);
    cudaGetSymbolAddress((void**)&p_partB,  g_partB);
    cudaGetSymbolAddress((void**)&p_WihT,   g_WihT);
    cudaGetSymbolAddress((void**)&p_WhhT,   g_WhhT);

    // per-replay prep
    init_state<<<(B_ * H_ + 255) / 256, 256>>>(h0);
    transpose_k<<<dim3((E_ + K_) / 32, G3H / 32), dim3(32, 8)>>>(W_ih, p_WihT, G3H, E_ + K_);
    transpose_k<<<dim3(H_ / 32, G3H / 32), dim3(32, 8)>>>(W_hh, p_WhhT, G3H, H_);
    gemm64<<<dim3(A_ / 128, (S_ * B_) / 64, 1), 256>>>(enc, Wk, p_keys, nullptr, K_, A_, 0);

    for (int t = 0; t < T; t++) {
        // qW = h @ Wq (split-K x8, partials in partA)
        gemm64<<<dim3(A_ / 128, 1, 8), 256>>>(p_h, Wq, p_partA, nullptr, H_, A_, 0);
        pre_attn<<<192, 256>>>(emb);

        attn_scores<<<(S_ * B_) / 8, 256>>>(v_att);
        softmax_ctx<<<B_, 256>>>(enc);

        // gi = rnn_in @ W_ih^T ; gh = h @ W_hh^T
        gemm64<<<dim3(G3H / 128, 1, 8), 256>>>(p_rnn, p_WihT, p_partA, nullptr, E_ + K_, G3H, 0);
        gemm64<<<dim3(G3H / 128, 1, 8), 256>>>(p_h, p_WhhT, p_partB, nullptr, H_, G3H, 0);
        gru_fused<<<B_ * H_ / 256, 256>>>(b_ih, b_hh);

        // hidden = tanh(mlp_in @ W1 + b1)
        gemm64<<<dim3(H_ / 128, 1, 8), 256>>>(p_mlp, W1, p_partA, nullptr, E_ + H_ + K_, H_, 0);
        reduce_split<<<(B_ * H_ + 255) / 256, 256>>>(p_hidden, p_partA, b1, H_, 8, 1);

        // logits = hidden @ W2 + b2
        gemm64<<<dim3(V_ / 128, 1, 1), 256>>>(p_hidden, W2, p_logits, b2, H_, V_, 0);

        softmax_v<<<B_, 512>>>(out, t, T);
    }
}

// round 4
// speedup vs baseline: 2.2399x; 1.1854x over previous
#include <cuda_runtime.h>
#include <math.h>

#define S_  64
#define B_  64
#define K_  512
#define H_  512
#define E_  512
#define A_  512
#define V_  32000
#define G3H 1536

// ---------------- scratch (static device memory; no allocations) ----------------
__device__ float g_keys[S_ * B_ * A_];          // keys_proj [s][b][a]
__device__ float g_rnn_in[B_ * (E_ + K_)];      // [x_emb | ctx]
__device__ float g_mlp_in[B_ * (E_ + H_ + K_)]; // [x_emb | h_new | ctx]
__device__ float g_h[B_ * H_];
__device__ float g_hidden[B_ * H_];
__device__ float g_logits[B_ * V_];
__device__ float g_partA[16 * B_ * G3H];        // split-K partials
__device__ float g_partB[16 * B_ * G3H];
__device__ float g_WihT[(E_ + K_) * G3H];       // W_ih^T
__device__ float g_WhhT[H_ * G3H];              // W_hh^T
__device__ int   g_tok[B_];

// ---------------- fast math ----------------
__device__ __forceinline__ float ftanh(float x) {
    float t = __expf(-2.f * fabsf(x));
    float r = __fdividef(1.f - t, 1.f + t);
    return copysignf(r, x);
}
__device__ __forceinline__ float fsigmoid(float x) {
    return __fdividef(1.f, 1.f + __expf(-x));
}

// ---------------- packed f32x2 FMA ----------------
__device__ __forceinline__ float2 ffma2(float2 a, float2 b, float2 c) {
    unsigned long long ua = *reinterpret_cast<unsigned long long*>(&a);
    unsigned long long ub = *reinterpret_cast<unsigned long long*>(&b);
    unsigned long long uc = *reinterpret_cast<unsigned long long*>(&c);
    unsigned long long ud;
    asm("fma.rn.f32x2 %0, %1, %2, %3;" : "=l"(ua) : "l"(ua), "l"(ub), "l"(uc));
    ud = ua;
    return *reinterpret_cast<float2*>(&ud);
}

// ============ generic NN GEMM (small): C[M,N]=A[M,K]@B[K,N], tile 64x128 ============
__device__ __forceinline__ void gemm_compute(
    const float (*As2)[130], const float (*Bs)[128],
    int m0, int bn, float2 acc[4][4])
{
#pragma unroll
    for (int kk = 0; kk < 16; kk++) {
        float2 ad[4];
#pragma unroll
        for (int i = 0; i < 4; i++)
            ad[i] = *(const float2*)&As2[kk][2 * (m0 + i)];
        float4 b0 = *(const float4*)&Bs[kk][bn];
        float4 b1 = *(const float4*)&Bs[kk][bn + 64];
        float2 bp[4];
        bp[0] = make_float2(b0.x, b0.y); bp[1] = make_float2(b0.z, b0.w);
        bp[2] = make_float2(b1.x, b1.y); bp[3] = make_float2(b1.z, b1.w);
#pragma unroll
        for (int i = 0; i < 4; i++)
#pragma unroll
            for (int j = 0; j < 4; j++)
                acc[i][j] = ffma2(ad[i], bp[j], acc[i][j]);
    }
}

__global__ void __launch_bounds__(256, 3)
gemm64(const float* __restrict__ A, const float* __restrict__ B,
       float* __restrict__ C, const float* __restrict__ bias,
       int K, int N, int act)
{
    __shared__ __align__(16) float As2[2][16][130];
    __shared__ __align__(16) float Bs[2][16][128];

    const int tid = threadIdx.x;
    const int Keff = K / gridDim.z;
    const float* Ap = A + (size_t)blockIdx.z * Keff;
    const float* Bp = B + (size_t)blockIdx.z * Keff * N;
    float* Cp = C + (size_t)blockIdx.z * 64 * N;

    const int m_base = blockIdx.y * 64;
    const int n_base = blockIdx.x * 128;

    const int ty = tid >> 4, tx = tid & 15;
    const int m0 = ty * 4;
    const int bn = tx * 4;

    const int am = tid >> 2, ak = (tid & 3) * 4;
    const int bk0 = tid >> 4;

    const float* Aload = Ap + (size_t)(m_base + am) * K + ak;
    const float* Bload = Bp + (size_t)bk0 * N + n_base + bn;

    float2 acc[4][4];
#pragma unroll
    for (int i = 0; i < 4; i++)
#pragma unroll
        for (int j = 0; j < 4; j++) acc[i][j] = make_float2(0.f, 0.f);

    float4 aR  = *(const float4*)Aload;
    float4 bR0 = *(const float4*)Bload;
    float4 bR1 = *(const float4*)(Bload + 64);

    *(float2*)&As2[0][ak + 0][2 * am] = make_float2(aR.x, aR.x);
    *(float2*)&As2[0][ak + 1][2 * am] = make_float2(aR.y, aR.y);
    *(float2*)&As2[0][ak + 2][2 * am] = make_float2(aR.z, aR.z);
    *(float2*)&As2[0][ak + 3][2 * am] = make_float2(aR.w, aR.w);
    *(float4*)&Bs[0][bk0][bn]      = bR0;
    *(float4*)&Bs[0][bk0][bn + 64] = bR1;
    __syncthreads();

    int buf = 0;
    for (int k0 = 16; k0 < Keff; k0 += 16) {
        float4 aN  = *(const float4*)(Aload + k0);
        float4 bN0 = *(const float4*)(Bload + (size_t)k0 * N);
        float4 bN1 = *(const float4*)(Bload + (size_t)k0 * N + 64);

        gemm_compute(As2[buf], Bs[buf], m0, bn, acc);

        int nb = buf ^ 1;
        *(float2*)&As2[nb][ak + 0][2 * am] = make_float2(aN.x, aN.x);
        *(float2*)&As2[nb][ak + 1][2 * am] = make_float2(aN.y, aN.y);
        *(float2*)&As2[nb][ak + 2][2 * am] = make_float2(aN.z, aN.z);
        *(float2*)&As2[nb][ak + 3][2 * am] = make_float2(aN.w, aN.w);
        *(float4*)&Bs[nb][bk0][bn]      = bN0;
        *(float4*)&Bs[nb][bk0][bn + 64] = bN1;
        __syncthreads();
        buf = nb;
    }
    gemm_compute(As2[buf], Bs[buf], m0, bn, acc);

#pragma unroll
    for (int i = 0; i < 4; i++) {
#pragma unroll
        for (int j = 0; j < 4; j++) {
            int n = n_base + bn + (j & 1) * 2 + (j >> 1) * 64;
            float2 v = acc[i][j];
            if (bias) { v.x += bias[n]; v.y += bias[n + 1]; }
            if (act)  { v.x = tanhf(v.x); v.y = tanhf(v.y); }
            *(float2*)&Cp[(size_t)(m_base + m0 + i) * N + n] = v;
        }
    }
}

// ============ logits GEMM: C[64,32000] = A[64,512] @ B[512,32000] + bias ============
// tile 64x256, 125 CTAs = one full wave, micro-tile 4m x 16n, dynamic smem.
#define ASL(bf,k,c) As2[(bf)*2080 + (k)*130 + (c)]
#define BSL(bf,k,c) Bs [(bf)*4096 + (k)*256 + (c)]

__device__ __forceinline__ void logits_compute(
    const float* __restrict__ As2, const float* __restrict__ Bs,
    int buf, int m0, int bn, float2 acc[4][8])
{
#pragma unroll
    for (int kk = 0; kk < 16; kk++) {
        float2 ad[4];
#pragma unroll
        for (int i = 0; i < 4; i++)
            ad[i] = *(const float2*)&ASL(buf, kk, 2 * (m0 + i));
#pragma unroll
        for (int g = 0; g < 4; g++) {
            float4 bq = *(const float4*)&BSL(buf, kk, bn + 64 * g);
            float2 b0 = make_float2(bq.x, bq.y);
            float2 b1 = make_float2(bq.z, bq.w);
#pragma unroll
            for (int i = 0; i < 4; i++) {
                acc[i][2 * g]     = ffma2(ad[i], b0, acc[i][2 * g]);
                acc[i][2 * g + 1] = ffma2(ad[i], b1, acc[i][2 * g + 1]);
            }
        }
    }
}

__global__ void __launch_bounds__(256, 1)
gemm_logits(const float* __restrict__ A, const float* __restrict__ B,
            float* __restrict__ C, const float* __restrict__ bias)
{
    extern __shared__ __align__(16) float sm[];
    float* As2 = sm;                 // [2][16][130]
    float* Bs  = sm + 2 * 16 * 130;  // [2][16][256]

    const int tid = threadIdx.x;
    const int N = V_, K = 512;
    const int n_base = blockIdx.x * 256;

    const int ty = tid >> 4, tx = tid & 15;
    const int m0 = ty * 4;
    const int bn = tx * 4;

    const int am = tid >> 2, ak = (tid & 3) * 4;
    const int bkr = tid >> 4;
    const int btx = (tid & 15) * 4;

    const float* Aload = A + (size_t)am * K + ak;
    const float* Bload = B + (size_t)bkr * N + n_base + btx;

    float2 acc[4][8];
#pragma unroll
    for (int i = 0; i < 4; i++)
#pragma unroll
        for (int j = 0; j < 8; j++) acc[i][j] = make_float2(0.f, 0.f);

    // preload tile 0
    float4 aR = *(const float4*)Aload;
    float4 bR[4];
#pragma unroll
    for (int q = 0; q < 4; q++) bR[q] = *(const float4*)(Bload + 64 * q);

    *(float2*)&ASL(0, ak + 0, 2 * am) = make_float2(aR.x, aR.x);
    *(float2*)&ASL(0, ak + 1, 2 * am) = make_float2(aR.y, aR.y);
    *(float2*)&ASL(0, ak + 2, 2 * am) = make_float2(aR.z, aR.z);
    *(float2*)&ASL(0, ak + 3, 2 * am) = make_float2(aR.w, aR.w);
#pragma unroll
    for (int q = 0; q < 4; q++) *(float4*)&BSL(0, bkr, btx + 64 * q) = bR[q];
    __syncthreads();

    int buf = 0;
    for (int k0 = 16; k0 < K; k0 += 16) {
        float4 aN = *(const float4*)(Aload + k0);
        float4 bN[4];
#pragma unroll
        for (int q = 0; q < 4; q++)
            bN[q] = *(const float4*)(Bload + (size_t)k0 * N + 64 * q);

        logits_compute(As2, Bs, buf, m0, bn, acc);

        int nb = buf ^ 1;
        *(float2*)&ASL(nb, ak + 0, 2 * am) = make_float2(aN.x, aN.x);
        *(float2*)&ASL(nb, ak + 1, 2 * am) = make_float2(aN.y, aN.y);
        *(float2*)&ASL(nb, ak + 2, 2 * am) = make_float2(aN.z, aN.z);
        *(float2*)&ASL(nb, ak + 3, 2 * am) = make_float2(aN.w, aN.w);
#pragma unroll
        for (int q = 0; q < 4; q++) *(float4*)&BSL(nb, bkr, btx + 64 * q) = bN[q];
        __syncthreads();
        buf = nb;
    }
    logits_compute(As2, Bs, buf, m0, bn, acc);

#pragma unroll
    for (int i = 0; i < 4; i++) {
#pragma unroll
        for (int g = 0; g < 4; g++) {
#pragma unroll
            for (int p = 0; p < 2; p++) {
                int n = n_base + bn + 64 * g + 2 * p;
                float2 v = acc[i][2 * g + p];
                v.x += bias[n]; v.y += bias[n + 1];
                *(float2*)&C[(size_t)(m0 + i) * N + n] = v;
            }
        }
    }
}

// Sum split-K partials, add bias, optional tanh.
__global__ void reduce_split(float* __restrict__ C, const float* __restrict__ part,
                             const float* __restrict__ bias, int N, int nz, int act)
{
    int idx = blockIdx.x * blockDim.x + threadIdx.x;
    if (idx >= 64 * N) return;
    int n = idx % N;
    float s = 0.f;
    for (int z = 0; z < nz; z++) s += part[(size_t)z * 64 * N + idx];
    if (bias) s += bias[n];
    if (act)  s = tanhf(s);
    C[idx] = s;
}

// out[c][r] = in[r][c]
__global__ void transpose_k(const float* __restrict__ in, float* __restrict__ out,
                            int R, int C)
{
    __shared__ float tile[32][33];
    int c = blockIdx.x * 32 + threadIdx.x;
    int r0 = blockIdx.y * 32;
    for (int i = threadIdx.y; i < 32; i += 8)
        tile[i][threadIdx.x] = in[(size_t)(r0 + i) * C + c];
    __syncthreads();
    int r2 = blockIdx.y * 32 + threadIdx.x;
    int c0 = blockIdx.x * 32;
    for (int i = threadIdx.y; i < 32; i += 8)
        out[(size_t)(c0 + i) * R + r2] = tile[threadIdx.x][i];
}

__global__ void init_state(const float* __restrict__ h0)
{
    int i = blockIdx.x * blockDim.x + threadIdx.x;
    if (i < B_) g_tok[i] = 1;                  // SOS
    if (i < B_ * H_) g_h[i] = h0[i];
}

// ============ fused attention: one block per b, 512 threads ============
// emb gather + qW split-K reduce + scores(tanh) + softmax_s + context
__global__ void __launch_bounds__(512, 2)
attn_fused(const float* __restrict__ emb, const float* __restrict__ v_att,
           const float* __restrict__ enc)
{
    __shared__ __align__(16) float s_q[A_];
    __shared__ __align__(16) float s_v[A_];
    __shared__ float s_sc[S_];
    __shared__ float s_attn[S_];

    const int b = blockIdx.x;
    const int tid = threadIdx.x;
    const int w = tid >> 5, lane = tid & 31;

    // phase 0: qW reduce (16 partials) + stage v_att + emb gather
    {
        float qs = 0.f;
#pragma unroll
        for (int z = 0; z < 16; z++)
            qs += g_partA[(size_t)z * B_ * A_ + b * A_ + tid];
        s_q[tid] = qs;
        s_v[tid] = v_att[tid];
        int tok = g_tok[b];
        float ev = emb[(size_t)tok * E_ + tid];
        g_rnn_in[b * (E_ + K_) + tid] = ev;
        g_mlp_in[b * (E_ + H_ + K_) + tid] = ev;
    }
    __syncthreads();

    // phase 1: scores — warp w handles s = 4w..4w+3
#pragma unroll
    for (int si = 0; si < 4; si++) {
        int s = w * 4 + si;
        const float4* kp = (const float4*)(g_keys + (size_t)(s * B_ + b) * A_);
        float acc = 0.f;
#pragma unroll
        for (int a4 = lane; a4 < A_ / 4; a4 += 32) {
            float4 k4 = kp[a4];
            float4 q4 = *(const float4*)&s_q[a4 * 4];
            float4 v4 = *(const float4*)&s_v[a4 * 4];
            acc += ftanh(q4.x + k4.x) * v4.x + ftanh(q4.y + k4.y) * v4.y
                 + ftanh(q4.z + k4.z) * v4.z + ftanh(q4.w + k4.w) * v4.w;
        }
#pragma unroll
        for (int o = 16; o; o >>= 1) acc += __shfl_xor_sync(0xffffffffu, acc, o);
        if (lane == 0) s_sc[s] = acc;
    }
    __syncthreads();

    // phase 2: softmax over 64 scores (warp 0)
    if (w == 0) {
        float a0 = s_sc[lane], a1 = s_sc[lane + 32];
        float mx = fmaxf(a0, a1);
#pragma unroll
        for (int o = 16; o; o >>= 1) mx = fmaxf(mx, __shfl_xor_sync(0xffffffffu, mx, o));
        float e0 = __expf(a0 - mx), e1 = __expf(a1 - mx);
        float ss = e0 + e1;
#pragma unroll
        for (int o = 16; o; o >>= 1) ss += __shfl_xor_sync(0xffffffffu, ss, o);
        float inv = __fdividef(1.f, ss);
        s_attn[lane] = e0 * inv;
        s_attn[lane + 32] = e1 * inv;
    }
    __syncthreads();

    // phase 3: ctx[k] = sum_s attn[s]*enc[s,b,k]
    {
        int k = tid;
        float acc = 0.f;
        const float* ep = enc + (size_t)b * K_ + k;
#pragma unroll 8
        for (int s2 = 0; s2 < S_; s2++)
            acc += s_attn[s2] * ep[(size_t)s2 * (B_ * K_)];
        g_rnn_in[b * (E_ + K_) + E_ + k] = acc;
        g_mlp_in[b * (E_ + H_ + K_) + E_ + H_ + k] = acc;
    }
}

// fused: sum gi/gh split-K partials (16 each) + biases + GRU + write h, mlp_in
__global__ void gru_fused(const float* __restrict__ b_ih, const float* __restrict__ b_hh)
{
    int idx = blockIdx.x * 256 + threadIdx.x;   // B_*H_ = 32768
    int b = idx >> 9, j = idx & 511;
    float gir = 0.f, giz = 0.f, gin = 0.f, ghr = 0.f, ghz = 0.f, ghn = 0.f;
#pragma unroll
    for (int z = 0; z < 16; z++) {
        const float* pa = g_partA + (size_t)z * B_ * G3H + b * G3H;
        const float* pb = g_partB + (size_t)z * B_ * G3H + b * G3H;
        gir += pa[j]; giz += pa[j + H_]; gin += pa[j + 2 * H_];
        ghr += pb[j]; ghz += pb[j + H_]; ghn += pb[j + 2 * H_];
    }
    gir += b_ih[j]; giz += b_ih[j + H_]; gin += b_ih[j + 2 * H_];
    ghr += b_hh[j]; ghz += b_hh[j + H_]; ghn += b_hh[j + 2 * H_];
    float r  = fsigmoid(gir + ghr);
    float z_ = fsigmoid(giz + ghz);
    float n  = ftanh(gin + r * ghn);
    float h  = g_h[idx];
    float hn = (1.f - z_) * n + z_ * h;
    g_h[idx] = hn;
    g_mlp_in[b * (E_ + H_ + K_) + E_ + j] = hn;
}

// one block per b (512 thr): max+argmax, sum-exp, write probs, feed next token
__global__ void softmax_v(float* __restrict__ out, int t, int T)
{
    int b = blockIdx.x;
    int tid = threadIdx.x;
    const float* lg = g_logits + (size_t)b * V_;
    float* op = out + ((size_t)b * T + t) * V_;
    int lane = tid & 31, w = tid >> 5;

    float bm = -1e30f; int bi = 0;
    for (int v = tid; v < V_; v += 512) {
        float x = lg[v];
        if (x > bm) { bm = x; bi = v; }
    }
    __shared__ float smax[16]; __shared__ int sidx[16]; __shared__ float ssum[16];
#pragma unroll
    for (int o = 16; o; o >>= 1) {
        float om = __shfl_xor_sync(0xffffffffu, bm, o);
        int   oi = __shfl_xor_sync(0xffffffffu, bi, o);
        if (om > bm || (om == bm && oi < bi)) { bm = om; bi = oi; }
    }
    if (!lane) { smax[w] = bm; sidx[w] = bi; }
    __syncthreads();
    if (tid == 0) {
        float M = smax[0]; int I = sidx[0];
        for (int i = 1; i < 16; i++)
            if (smax[i] > M || (smax[i] == M && sidx[i] < I)) { M = smax[i]; I = sidx[i]; }
        smax[0] = M;
        g_tok[b] = I;
    }
    __syncthreads();
    float mx = smax[0];

    float s = 0.f;
    for (int v = tid; v < V_; v += 512) s += __expf(lg[v] - mx);
#pragma unroll
    for (int o = 16; o; o >>= 1) s += __shfl_xor_sync(0xffffffffu, s, o);
    if (!lane) ssum[w] = s;
    __syncthreads();
    if (tid == 0) {
        float tt = 0.f;
        for (int i = 0; i < 16; i++) tt += ssum[i];
        ssum[0] = tt;
    }
    __syncthreads();
    float inv = __fdividef(1.f, ssum[0]);
    for (int v = tid; v < V_; v += 512) op[v] = __expf(lg[v] - mx) * inv;
}

// ---------------- launch ----------------
extern "C" void kernel_launch(void* const* d_in, const int* in_sizes, int n_in,
                              void* d_out, int out_size)
{
    const float* enc   = (const float*)d_in[0];
    const float* h0    = (const float*)d_in[1];
    const float* emb   = (const float*)d_in[2];
    const float* Wq    = (const float*)d_in[3];
    const float* Wk    = (const float*)d_in[4];
    const float* v_att = (const float*)d_in[5];
    const float* W_ih  = (const float*)d_in[6];
    const float* W_hh  = (const float*)d_in[7];
    const float* b_ih  = (const float*)d_in[8];
    const float* b_hh  = (const float*)d_in[9];
    const float* W1    = (const float*)d_in[10];
    const float* b1    = (const float*)d_in[11];
    const float* W2    = (const float*)d_in[12];
    const float* b2    = (const float*)d_in[13];
    float* out = (float*)d_out;
    const int T = out_size / (B_ * V_);

    float *p_keys, *p_rnn, *p_mlp, *p_h, *p_hidden, *p_logits,
          *p_partA, *p_partB, *p_WihT, *p_WhhT;
    cudaGetSymbolAddress((void**)&p_keys,   g_keys);
    cudaGetSymbolAddress((void**)&p_rnn,    g_rnn_in);
    cudaGetSymbolAddress((void**)&p_mlp,    g_mlp_in);
    cudaGetSymbolAddress((void**)&p_h,      g_h);
    cudaGetSymbolAddress((void**)&p_hidden, g_hidden);
    cudaGetSymbolAddress((void**)&p_logits, g_logits);
    cudaGetSymbolAddress((void**)&p_partA,  g_partA);
    cudaGetSymbolAddress((void**)&p_partB,  g_partB);
    cudaGetSymbolAddress((void**)&p_WihT,   g_WihT);
    cudaGetSymbolAddress((void**)&p_WhhT,   g_WhhT);

    const int LOGITS_SMEM = (2 * 16 * 130 + 2 * 16 * 256) * 4;  // 49408 B
    cudaFuncSetAttribute(gemm_logits, cudaFuncAttributeMaxDynamicSharedMemorySize,
                         LOGITS_SMEM);

    // per-replay prep
    init_state<<<(B_ * H_ + 255) / 256, 256>>>(h0);
    transpose_k<<<dim3((E_ + K_) / 32, G3H / 32), dim3(32, 8)>>>(W_ih, p_WihT, G3H, E_ + K_);
    transpose_k<<<dim3(H_ / 32, G3H / 32), dim3(32, 8)>>>(W_hh, p_WhhT, G3H, H_);
    gemm64<<<dim3(A_ / 128, (S_ * B_) / 64, 1), 256>>>(enc, Wk, p_keys, nullptr, K_, A_, 0);

    for (int t = 0; t < T; t++) {
        // qW = h @ Wq (split-K x16 -> partA)
        gemm64<<<dim3(A_ / 128, 1, 16), 256>>>(p_h, Wq, p_partA, nullptr, H_, A_, 0);
        attn_fused<<<B_, 512>>>(emb, v_att, enc);

        // gi = rnn_in @ W_ih^T (x16) ; gh = h @ W_hh^T (x16)
        gemm64<<<dim3(G3H / 128, 1, 16), 256>>>(p_rnn, p_WihT, p_partA, nullptr, E_ + K_, G3H, 0);
        gemm64<<<dim3(G3H / 128, 1, 16), 256>>>(p_h, p_WhhT, p_partB, nullptr, H_, G3H, 0);
        gru_fused<<<B_ * H_ / 256, 256>>>(b_ih, b_hh);

        // hidden = tanh(mlp_in @ W1 + b1)  (split-K x32, Keff=48)
        gemm64<<<dim3(H_ / 128, 1, 32), 256>>>(p_mlp, W1, p_partA, nullptr, E_ + H_ + K_, H_, 0);
        reduce_split<<<(B_ * H_ + 255) / 256, 256>>>(p_hidden, p_partA, b1, H_, 32, 1);

        // logits = hidden @ W2 + b2  (64x256 tiles, 125 CTAs = one wave)
        gemm_logits<<<V_ / 256, 256, LOGITS_SMEM>>>(p_hidden, W2, p_logits, b2);

        softmax_v<<<B_, 512>>>(out, t, T);
    }
}